// round 7
// baseline (speedup 1.0000x reference)
#include <cuda_runtime.h>
#include <cstdint>

// out[b, 0:128]   = x[b, :]                       for b < B
// out[b, 128:256] = sum_{e: dst[e]==b} x[src[e]]
//
// Pipeline:
//   memset:  zero overflow counter only (4 bytes). g_cnt is self-cleaned by
//            main_kernel each call (counters are statically zero-initialized,
//            and every call restores them -> replay-invariant).
//   K1 bin:  ELL binning by destination (scalar, one edge per thread).
//   K2 main: HALF-warp per row: 16 lanes x 2 float4 chains per lane ->
//            2 independent gathers in flight per lane with no register
//            buffering. 2 rows per warp. Fused copy of x[b]; overflow rows
//            (deg > SLOTS) scan the overflow list in-warp. Plain STG stores.

#define NFEAT   128
#define ROW_OUT 256
#define MAX_E   640000
#define B_MAX   65536
#define SLOTS   32

__device__ int  g_cnt[B_MAX];
__device__ int  g_ell[B_MAX * SLOTS];
__device__ int2 g_ovf[MAX_E];
__device__ int  g_ovf_count;

__global__ void bin_kernel(const int* __restrict__ ei, int E, int B) {
    int i = blockIdx.x * blockDim.x + threadIdx.x;
    if (i >= E) return;
    int d = __ldg(ei + E + i);
    if ((unsigned)d < (unsigned)B) {
        int s = __ldg(ei + i);
        int k = atomicAdd(&g_cnt[d], 1);
        if (k < SLOTS) {
            g_ell[d * SLOTS + k] = s;
        } else {
            int p = atomicAdd(&g_ovf_count, 1);
            g_ovf[p] = make_int2(s, d);
        }
    }
}

__global__ __launch_bounds__(256, 6)
void main_kernel(const float* __restrict__ x,
                 float* __restrict__ out,
                 int B) {
    int gtid = blockIdx.x * blockDim.x + threadIdx.x;
    int warp = gtid >> 5;
    int lane = threadIdx.x & 31;
    int hl   = lane & 15;                 // lane within half-warp
    int b    = warp * 2 + ((lane >> 4) & 1);
    if (b >= B) return;
    unsigned hmask = 0xFFFFu << (lane & 16);   // this half-warp's mask

    int c_raw = g_cnt[b];
    int c = c_raw < SLOTS ? c_raw : SLOTS;
    if (hl == 0) g_cnt[b] = 0;            // self-clean for the next replay

    // 16 lanes hold the 32 ELL slots: lane hl owns slots hl and hl+16.
    int s0 = (hl      < c) ? g_ell[b * SLOTS + hl]      : 0;
    int s1 = (hl + 16 < c) ? g_ell[b * SLOTS + hl + 16] : 0;

    // Own row, two chains per lane (issued early, overlap the gathers).
    const float4* xb = reinterpret_cast<const float4*>(x + (size_t)b * NFEAT);
    float4 mine0 = __ldg(xb + hl);
    float4 mine1 = __ldg(xb + hl + 16);

    float4 acc0 = make_float4(0.f, 0.f, 0.f, 0.f);
    float4 acc1 = make_float4(0.f, 0.f, 0.f, 0.f);

    for (int k = 0; k < c; k++) {
        int se = __shfl_sync(hmask, (k < 16) ? s0 : s1, k & 15, 16);
        const float4* xs = reinterpret_cast<const float4*>(
                               x + (size_t)se * NFEAT);
        float4 v0 = __ldg(xs + hl);        // two independent loads ->
        float4 v1 = __ldg(xs + hl + 16);   // MLP 2 per lane, no buffering
        acc0.x += v0.x; acc0.y += v0.y; acc0.z += v0.z; acc0.w += v0.w;
        acc1.x += v1.x; acc1.y += v1.y; acc1.z += v1.z; acc1.w += v1.w;
    }

    // Rare path: degree exceeded SLOTS -> extras live in the overflow list.
    if (c_raw > SLOTS) {
        int n = g_ovf_count;
        for (int e = 0; e < n; e++) {
            int2 ed = g_ovf[e];
            if (ed.y == b) {
                const float4* xs = reinterpret_cast<const float4*>(
                                       x + (size_t)ed.x * NFEAT);
                float4 v0 = __ldg(xs + hl);
                float4 v1 = __ldg(xs + hl + 16);
                acc0.x += v0.x; acc0.y += v0.y; acc0.z += v0.z; acc0.w += v0.w;
                acc1.x += v1.x; acc1.y += v1.y; acc1.z += v1.z; acc1.w += v1.w;
            }
        }
    }

    float4* orow = reinterpret_cast<float4*>(out + (size_t)b * ROW_OUT);
    orow[hl]           = mine0;
    orow[hl + 16]      = mine1;
    orow[32 + hl]      = acc0;
    orow[32 + hl + 16] = acc1;
}

extern "C" void kernel_launch(void* const* d_in, const int* in_sizes, int n_in,
                              void* d_out, int out_size) {
    const float* x        = (const float*)d_in[0];
    const int*   edge_idx = (const int*)d_in[1];
    float*       out      = (float*)d_out;

    int B = out_size / ROW_OUT;          // 50000
    int E = in_sizes[1] / 2;             // 640000

    // Only the 4-byte overflow counter needs a memset node; g_cnt is
    // self-cleaned by main_kernel.
    void* p_ovfc = nullptr;
    cudaGetSymbolAddress(&p_ovfc, g_ovf_count);
    cudaMemsetAsync(p_ovfc, 0, sizeof(int));

    {   // K1: ELL binning (one edge per thread)
        int threads = 256;
        int blocks = (E + threads - 1) / threads;
        bin_kernel<<<blocks, threads>>>(edge_idx, E, B);
    }
    {   // K2: main fused gather-accumulate-store, half-warp per row
        int warps_needed = (B + 1) / 2;
        int threads = 256;                          // 8 warps/block
        int blocks = (warps_needed + 7) / 8;
        main_kernel<<<blocks, threads>>>(x, out, B);
    }
}